// round 3
// baseline (speedup 1.0000x reference)
#include <cuda_runtime.h>
#include <cuda_bf16.h>
#include <math.h>

// Problem constants (fixed by the dataset)
#define MN 100000       // nodes
#define EE 1600000      // edges
#define NF 133          // input feature dim (layer 0 K)
#define HD 128          // hidden size

// ---------------------------------------------------------------------------
// Static scratch (no allocations allowed in kernel_launch)
// ---------------------------------------------------------------------------
__device__ float g_g[(size_t)MN * HD];   // g = (h @ W) * dinv[row]
__device__ float g_a[(size_t)MN * HD];   // scatter accumulator
__device__ float g_h[(size_t)MN * HD];   // layer output (inter-layer buffer)
__device__ float g_deg[MN];
__device__ float g_dinv[MN];

// ---------------------------------------------------------------------------
// Degree / dinv
// ---------------------------------------------------------------------------
__global__ void deg_init_kernel() {
    int i = blockIdx.x * blockDim.x + threadIdx.x;
    if (i < MN) g_deg[i] = 1.0f;   // self-loop
}

__global__ void deg_acc_kernel(const int* __restrict__ dst) {
    int e = blockIdx.x * blockDim.x + threadIdx.x;
    if (e < EE) {
        int d = dst[e];
        if (d >= 0 && d < MN) atomicAdd(&g_deg[d], 1.0f);
    }
}

__global__ void dinv_kernel() {
    int i = blockIdx.x * blockDim.x + threadIdx.x;
    if (i < MN) g_dinv[i] = rsqrtf(g_deg[i]);
}

// ---------------------------------------------------------------------------
// Zero the scatter accumulator (float4 stores)
// ---------------------------------------------------------------------------
__global__ void zero_a_kernel() {
    int idx = blockIdx.x * blockDim.x + threadIdx.x;   // over MN*32 float4 slots
    if (idx < MN * 32) {
        float4 z = make_float4(0.f, 0.f, 0.f, 0.f);
        *(float4*)&g_a[(size_t)idx * 4] = z;
    }
}

// ---------------------------------------------------------------------------
// SGEMM with epilogue scale: g_g[r, :] = (A[r, :] @ W) * dinv[r]
// A: [MN, K] row-major (K = 133 or 128), W: [K, 128] row-major.
// BM=128, BN=128 (= full H), BK=8, 256 threads, 8x8 per-thread tile.
// Ain == nullptr means "read from g_h" (inter-layer buffer).
// ---------------------------------------------------------------------------
__global__ void __launch_bounds__(256) gemm_scale_kernel(
    const float* __restrict__ Ain, const float* __restrict__ W, int K)
{
    const float* A = Ain ? Ain : g_h;

    __shared__ float As[8][132];   // padded: conflict-spread, row base 16B aligned
    __shared__ float Bs[8][132];

    const int tid  = threadIdx.x;
    const int row0 = blockIdx.x * 128;
    const int tx   = tid & 15;     // column group (8 cols)
    const int ty   = tid >> 4;     // row group (8 rows)

    float acc[8][8];
#pragma unroll
    for (int i = 0; i < 8; i++)
#pragma unroll
        for (int j = 0; j < 8; j++) acc[i][j] = 0.f;

    for (int k0 = 0; k0 < K; k0 += 8) {
        // --- load A tile (128 rows x 8 k), 4 scalars per thread ---
#pragma unroll
        for (int i = 0; i < 4; i++) {
            int e  = tid * 4 + i;
            int r  = e >> 3;
            int kk = e & 7;
            int gr = row0 + r;
            int gk = k0 + kk;
            float v = 0.f;
            if (gr < MN && gk < K) v = A[(size_t)gr * K + gk];
            As[kk][r] = v;
        }
        // --- load W tile (8 k x 128 cols), one float4 per thread ---
        {
            int kk  = tid >> 5;
            int col = (tid & 31) * 4;
            int gk  = k0 + kk;
            float4 v = make_float4(0.f, 0.f, 0.f, 0.f);
            if (gk < K) v = *(const float4*)&W[(size_t)gk * HD + col];
            *(float4*)&Bs[kk][col] = v;
        }
        __syncthreads();

#pragma unroll
        for (int k = 0; k < 8; k++) {
            float ar[8], br[8];
            float4 a0 = *(const float4*)&As[k][ty * 8];
            float4 a1 = *(const float4*)&As[k][ty * 8 + 4];
            float4 b0 = *(const float4*)&Bs[k][tx * 8];
            float4 b1 = *(const float4*)&Bs[k][tx * 8 + 4];
            ar[0]=a0.x; ar[1]=a0.y; ar[2]=a0.z; ar[3]=a0.w;
            ar[4]=a1.x; ar[5]=a1.y; ar[6]=a1.z; ar[7]=a1.w;
            br[0]=b0.x; br[1]=b0.y; br[2]=b0.z; br[3]=b0.w;
            br[4]=b1.x; br[5]=b1.y; br[6]=b1.z; br[7]=b1.w;
#pragma unroll
            for (int i = 0; i < 8; i++)
#pragma unroll
                for (int j = 0; j < 8; j++)
                    acc[i][j] += ar[i] * br[j];
        }
        __syncthreads();
    }

    // --- epilogue: scale by dinv[row], store to g_g ---
#pragma unroll
    for (int i = 0; i < 8; i++) {
        int gr = row0 + ty * 8 + i;
        if (gr >= MN) continue;
        float di = g_dinv[gr];
        float4 o0, o1;
        o0.x = acc[i][0] * di; o0.y = acc[i][1] * di;
        o0.z = acc[i][2] * di; o0.w = acc[i][3] * di;
        o1.x = acc[i][4] * di; o1.y = acc[i][5] * di;
        o1.z = acc[i][6] * di; o1.w = acc[i][7] * di;
        float* p = &g_g[(size_t)gr * HD + tx * 8];
        *(float4*)p       = o0;
        *(float4*)(p + 4) = o1;
    }
}

// ---------------------------------------------------------------------------
// Edge scatter: one warp per edge; lane handles 4 floats.
// g_a[dst, :] += g_g[src, :]  -- atomicAdd with unused result lowers to REDG
// ---------------------------------------------------------------------------
__global__ void __launch_bounds__(256) scatter_kernel(
    const int* __restrict__ src, const int* __restrict__ dst)
{
    int gw   = (blockIdx.x * blockDim.x + threadIdx.x) >> 5;
    int lane = threadIdx.x & 31;
    if (gw >= EE) return;
    int s = src[gw];
    int d = dst[gw];
    if ((unsigned)s >= MN || (unsigned)d >= MN) return;
    float4 v = *(const float4*)&g_g[(size_t)s * HD + lane * 4];
    float* p = &g_a[(size_t)d * HD + lane * 4];
    atomicAdd(p + 0, v.x);
    atomicAdd(p + 1, v.y);
    atomicAdd(p + 2, v.z);
    atomicAdd(p + 3, v.w);
}

// ---------------------------------------------------------------------------
// Finalize: dest[r, c] = tanh(dinv[r] * (a[r,c] + g[r,c]) + b[c])
// dest == nullptr means "write to g_h" (inter-layer buffer).
// ---------------------------------------------------------------------------
__global__ void __launch_bounds__(256) finalize_kernel(
    const float* __restrict__ b, float* __restrict__ dest_in)
{
    float* dest = dest_in ? dest_in : g_h;
    int idx = blockIdx.x * blockDim.x + threadIdx.x;   // MN*32 float4 slots
    if (idx >= MN * 32) return;
    int row = idx >> 5;
    int c   = (idx & 31) * 4;
    float di = g_dinv[row];
    const float4 av = *(const float4*)&g_a[(size_t)row * HD + c];
    const float4 gv = *(const float4*)&g_g[(size_t)row * HD + c];
    const float4 bv = *(const float4*)&b[c];
    float4 o;
    o.x = tanhf(di * (av.x + gv.x) + bv.x);
    o.y = tanhf(di * (av.y + gv.y) + bv.y);
    o.z = tanhf(di * (av.z + gv.z) + bv.z);
    o.w = tanhf(di * (av.w + gv.w) + bv.w);
    *(float4*)&dest[(size_t)row * HD + c] = o;
}

// ---------------------------------------------------------------------------
// Launch
// ---------------------------------------------------------------------------
extern "C" void kernel_launch(void* const* d_in, const int* in_sizes, int n_in,
                              void* d_out, int out_size)
{
    const float* x  = (const float*)d_in[0];
    const int*   ei = (const int*)d_in[1];      // edge_index downcast to int32 by harness
    const float* W[4] = { (const float*)d_in[2], (const float*)d_in[4],
                          (const float*)d_in[6], (const float*)d_in[8] };
    const float* B[4] = { (const float*)d_in[3], (const float*)d_in[5],
                          (const float*)d_in[7], (const float*)d_in[9] };
    const int* src = ei;
    const int* dst = ei + EE;
    float* out = (float*)d_out;

    const int TPB = 256;
    const int nb_node  = (MN + TPB - 1) / TPB;                 // 391
    const int nb_edge  = (EE + TPB - 1) / TPB;                 // 6250
    const int nb_vec   = (MN * 32 + TPB - 1) / TPB;            // 12500
    const int nb_gemm  = (MN + 127) / 128;                     // 782
    const int nb_scat  = (int)(((long long)EE * 32 + TPB - 1) / TPB);  // 200000

    // degrees + dinv (recomputed every launch; deterministic)
    deg_init_kernel<<<nb_node, TPB>>>();
    deg_acc_kernel<<<nb_edge, TPB>>>(dst);
    dinv_kernel<<<nb_node, TPB>>>();

    for (int l = 0; l < 4; l++) {
        const float* A = (l == 0) ? x : nullptr;   // nullptr -> g_h
        int K = (l == 0) ? NF : HD;
        float* dest = (l == 3) ? out : nullptr;    // nullptr -> g_h

        zero_a_kernel<<<nb_vec, TPB>>>();
        gemm_scale_kernel<<<nb_gemm, TPB>>>(A, W[l], K);
        scatter_kernel<<<nb_scat, TPB>>>(src, dst);
        finalize_kernel<<<nb_vec, TPB>>>(B[l], dest);
    }
}

// round 4
// speedup vs baseline: 2.1109x; 2.1109x over previous
#include <cuda_runtime.h>
#include <cuda_bf16.h>
#include <math.h>

// Problem constants (fixed by the dataset)
#define MN 100000       // nodes
#define EE 1600000      // edges
#define NF 133          // input feature dim (layer 0 K)
#define HD 128          // hidden size
#define NB_SCAN ((MN + 255) / 256)   // 391 blocks in node-scan

// ---------------------------------------------------------------------------
// Static scratch (no allocations allowed anywhere)
// ---------------------------------------------------------------------------
__device__ float g_g[(size_t)MN * HD];     // g = (h @ W) * dinv[row]
__device__ float g_h[(size_t)MN * HD];     // inter-layer buffer
__device__ float g_dinv[MN];
__device__ int   g_cnt[MN];                // in-degree counts
__device__ int   g_rowptr[MN + 1];         // CSR row pointers (dst-indexed)
__device__ int   g_cursor[MN];             // fill cursors
__device__ int   g_esrc[EE];               // CSR column indices (src node ids)
__device__ int   g_blocksum[NB_SCAN];
__device__ int   g_blockoff[NB_SCAN];

// ---------------------------------------------------------------------------
// CSR build: counts -> scan -> fill
// ---------------------------------------------------------------------------
__global__ void cnt_init_kernel() {
    int i = blockIdx.x * blockDim.x + threadIdx.x;
    if (i < MN) g_cnt[i] = 0;
}

__global__ void count_kernel(const int* __restrict__ dst) {
    int e = blockIdx.x * blockDim.x + threadIdx.x;
    if (e < EE) {
        int d = dst[e];
        if ((unsigned)d < MN) atomicAdd(&g_cnt[d], 1);
    }
}

// per-block sum of counts -> blocksum; also dinv = rsqrt(cnt+1)
__global__ void scan_block_kernel() {
    __shared__ int s[256];
    int t = threadIdx.x;
    int i = blockIdx.x * 256 + t;
    int v = (i < MN) ? g_cnt[i] : 0;
    if (i < MN) g_dinv[i] = rsqrtf((float)v + 1.0f);
    s[t] = v;
    __syncthreads();
    for (int off = 128; off > 0; off >>= 1) {
        if (t < off) s[t] += s[t + off];
        __syncthreads();
    }
    if (t == 0) g_blocksum[blockIdx.x] = s[0];
}

// single-block exclusive scan of blocksums (NB_SCAN = 391 <= 512)
__global__ void scan_top_kernel() {
    __shared__ int s[512];
    int t = threadIdx.x;
    int v = (t < NB_SCAN) ? g_blocksum[t] : 0;
    s[t] = v;
    __syncthreads();
    for (int off = 1; off < 512; off <<= 1) {
        int x = (t >= off) ? s[t - off] : 0;
        __syncthreads();
        s[t] += x;
        __syncthreads();
    }
    if (t < NB_SCAN) g_blockoff[t] = s[t] - v;        // exclusive
    if (t == 511)    g_rowptr[MN]  = s[511];          // total
}

// per-block exclusive scan + global offset -> rowptr, cursor
__global__ void scan_apply_kernel() {
    __shared__ int s[256];
    int t = threadIdx.x;
    int i = blockIdx.x * 256 + t;
    int v = (i < MN) ? g_cnt[i] : 0;
    s[t] = v;
    __syncthreads();
    for (int off = 1; off < 256; off <<= 1) {
        int x = (t >= off) ? s[t - off] : 0;
        __syncthreads();
        s[t] += x;
        __syncthreads();
    }
    if (i < MN) {
        int rp = g_blockoff[blockIdx.x] + s[t] - v;   // exclusive prefix
        g_rowptr[i] = rp;
        g_cursor[i] = rp;
    }
}

__global__ void fill_kernel(const int* __restrict__ src, const int* __restrict__ dst) {
    int e = blockIdx.x * blockDim.x + threadIdx.x;
    if (e < EE) {
        int d = dst[e];
        int s = src[e];
        if ((unsigned)d < MN && (unsigned)s < MN) {
            int pos = atomicAdd(&g_cursor[d], 1);
            g_esrc[pos] = s;
        }
    }
}

// ---------------------------------------------------------------------------
// SGEMM with epilogue scale: g_g[r, :] = (A[r, :] @ W) * dinv[r]
// BM=128, BN=128, BK=8, 256 threads, 8x8 per-thread tile.
// Ain == nullptr means "read from g_h".
// ---------------------------------------------------------------------------
__global__ void __launch_bounds__(256) gemm_scale_kernel(
    const float* __restrict__ Ain, const float* __restrict__ W, int K)
{
    const float* A = Ain ? Ain : g_h;

    __shared__ float As[8][132];
    __shared__ float Bs[8][132];

    const int tid  = threadIdx.x;
    const int row0 = blockIdx.x * 128;
    const int tx   = tid & 15;
    const int ty   = tid >> 4;

    float acc[8][8];
#pragma unroll
    for (int i = 0; i < 8; i++)
#pragma unroll
        for (int j = 0; j < 8; j++) acc[i][j] = 0.f;

    for (int k0 = 0; k0 < K; k0 += 8) {
#pragma unroll
        for (int i = 0; i < 4; i++) {
            int e  = tid * 4 + i;
            int r  = e >> 3;
            int kk = e & 7;
            int gr = row0 + r;
            int gk = k0 + kk;
            float v = 0.f;
            if (gr < MN && gk < K) v = A[(size_t)gr * K + gk];
            As[kk][r] = v;
        }
        {
            int kk  = tid >> 5;
            int col = (tid & 31) * 4;
            int gk  = k0 + kk;
            float4 v = make_float4(0.f, 0.f, 0.f, 0.f);
            if (gk < K) v = *(const float4*)&W[(size_t)gk * HD + col];
            *(float4*)&Bs[kk][col] = v;
        }
        __syncthreads();

#pragma unroll
        for (int k = 0; k < 8; k++) {
            float ar[8], br[8];
            float4 a0 = *(const float4*)&As[k][ty * 8];
            float4 a1 = *(const float4*)&As[k][ty * 8 + 4];
            float4 b0 = *(const float4*)&Bs[k][tx * 8];
            float4 b1 = *(const float4*)&Bs[k][tx * 8 + 4];
            ar[0]=a0.x; ar[1]=a0.y; ar[2]=a0.z; ar[3]=a0.w;
            ar[4]=a1.x; ar[5]=a1.y; ar[6]=a1.z; ar[7]=a1.w;
            br[0]=b0.x; br[1]=b0.y; br[2]=b0.z; br[3]=b0.w;
            br[4]=b1.x; br[5]=b1.y; br[6]=b1.z; br[7]=b1.w;
#pragma unroll
            for (int i = 0; i < 8; i++)
#pragma unroll
                for (int j = 0; j < 8; j++)
                    acc[i][j] += ar[i] * br[j];
        }
        __syncthreads();
    }

#pragma unroll
    for (int i = 0; i < 8; i++) {
        int gr = row0 + ty * 8 + i;
        if (gr >= MN) continue;
        float di = g_dinv[gr];
        float4 o0, o1;
        o0.x = acc[i][0] * di; o0.y = acc[i][1] * di;
        o0.z = acc[i][2] * di; o0.w = acc[i][3] * di;
        o1.x = acc[i][4] * di; o1.y = acc[i][5] * di;
        o1.z = acc[i][6] * di; o1.w = acc[i][7] * di;
        float* p = &g_g[(size_t)gr * HD + tx * 8];
        *(float4*)p       = o0;
        *(float4*)(p + 4) = o1;
    }
}

// ---------------------------------------------------------------------------
// Gather + finalize: one warp per dst node.
//   acc = g[i] + sum_{j in CSR row i} g[j]
//   dest[i] = tanh(dinv[i] * acc + b)
// dest == nullptr means "write to g_h".
// ---------------------------------------------------------------------------
__global__ void __launch_bounds__(256) gather_kernel(
    const float* __restrict__ b, float* __restrict__ dest_in)
{
    float* dest = dest_in ? dest_in : g_h;
    int warp = (blockIdx.x * blockDim.x + threadIdx.x) >> 5;
    int lane = threadIdx.x & 31;
    if (warp >= MN) return;
    const int i  = warp;
    const int c  = lane * 4;
    const int r0 = g_rowptr[i];
    const int r1 = g_rowptr[i + 1];

    // self term
    float4 acc = *(const float4*)&g_g[(size_t)i * HD + c];

    int e = r0;
    // unroll by 4 for MLP
    for (; e + 4 <= r1; e += 4) {
        int s0 = g_esrc[e + 0];
        int s1 = g_esrc[e + 1];
        int s2 = g_esrc[e + 2];
        int s3 = g_esrc[e + 3];
        float4 v0 = *(const float4*)&g_g[(size_t)s0 * HD + c];
        float4 v1 = *(const float4*)&g_g[(size_t)s1 * HD + c];
        float4 v2 = *(const float4*)&g_g[(size_t)s2 * HD + c];
        float4 v3 = *(const float4*)&g_g[(size_t)s3 * HD + c];
        acc.x += v0.x + v1.x + v2.x + v3.x;
        acc.y += v0.y + v1.y + v2.y + v3.y;
        acc.z += v0.z + v1.z + v2.z + v3.z;
        acc.w += v0.w + v1.w + v2.w + v3.w;
    }
    for (; e < r1; e++) {
        int s = g_esrc[e];
        float4 v = *(const float4*)&g_g[(size_t)s * HD + c];
        acc.x += v.x; acc.y += v.y; acc.z += v.z; acc.w += v.w;
    }

    float di = g_dinv[i];
    float4 bv = *(const float4*)&b[c];
    float4 o;
    o.x = tanhf(di * acc.x + bv.x);
    o.y = tanhf(di * acc.y + bv.y);
    o.z = tanhf(di * acc.z + bv.z);
    o.w = tanhf(di * acc.w + bv.w);
    *(float4*)&dest[(size_t)i * HD + c] = o;
}

// ---------------------------------------------------------------------------
// Launch
// ---------------------------------------------------------------------------
extern "C" void kernel_launch(void* const* d_in, const int* in_sizes, int n_in,
                              void* d_out, int out_size)
{
    const float* x  = (const float*)d_in[0];
    const int*   ei = (const int*)d_in[1];      // edge_index (int32 in harness)
    const float* W[4] = { (const float*)d_in[2], (const float*)d_in[4],
                          (const float*)d_in[6], (const float*)d_in[8] };
    const float* B[4] = { (const float*)d_in[3], (const float*)d_in[5],
                          (const float*)d_in[7], (const float*)d_in[9] };
    const int* src = ei;
    const int* dst = ei + EE;
    float* out = (float*)d_out;

    const int TPB = 256;
    const int nb_node = (MN + TPB - 1) / TPB;                 // 391
    const int nb_edge = (EE + TPB - 1) / TPB;                 // 6250
    const int nb_gemm = (MN + 127) / 128;                     // 782
    const int nb_gath = (int)(((long long)MN * 32 + TPB - 1) / TPB);  // 12500

    // CSR build (recomputed every launch; deterministic structure)
    cnt_init_kernel<<<nb_node, TPB>>>();
    count_kernel<<<nb_edge, TPB>>>(dst);
    scan_block_kernel<<<NB_SCAN, 256>>>();
    scan_top_kernel<<<1, 512>>>();
    scan_apply_kernel<<<NB_SCAN, 256>>>();
    fill_kernel<<<nb_edge, TPB>>>(src, dst);

    for (int l = 0; l < 4; l++) {
        const float* A = (l == 0) ? x : nullptr;   // nullptr -> g_h
        int K = (l == 0) ? NF : HD;
        float* dest = (l == 3) ? out : nullptr;    // nullptr -> g_h

        gemm_scale_kernel<<<nb_gemm, TPB>>>(A, W[l], K);
        gather_kernel<<<nb_gath, TPB>>>(B[l], dest);
    }
}

// round 5
// speedup vs baseline: 3.5163x; 1.6658x over previous
#include <cuda_runtime.h>
#include <cuda_bf16.h>
#include <math.h>

// Problem constants (fixed by the dataset)
#define MN 100000       // nodes
#define EE 1600000      // edges
#define NF 133          // input feature dim (layer 0 K)
#define HD 128          // hidden size
#define NB_SCAN ((MN + 255) / 256)   // 391 blocks in node-scan

// Packed f32x2 helpers (Blackwell FFMA2 — only reachable via PTX)
#define PACK_DUP(d, a)      asm("mov.b64 %0, {%1, %1};" : "=l"(d) : "f"(a))
#define UNPACK2(lo, hi, v)  asm("mov.b64 {%0, %1}, %2;" : "=f"(lo), "=f"(hi) : "l"(v))
#define FFMA2(d, a, b)      asm("fma.rn.f32x2 %0, %1, %2, %0;" : "+l"(d) : "l"(a), "l"(b))

// ---------------------------------------------------------------------------
// Static scratch (no allocations allowed anywhere)
// ---------------------------------------------------------------------------
__device__ float g_g[(size_t)MN * HD];     // g = (h @ W) * dinv[row]
__device__ float g_h[(size_t)MN * HD];     // inter-layer buffer
__device__ float g_dinv[MN];
__device__ int   g_cnt[MN];                // in-degree counts
__device__ int   g_rowptr[MN + 1];         // CSR row pointers (dst-indexed)
__device__ int   g_cursor[MN];             // fill cursors
__device__ int   g_esrc[EE];               // CSR column indices (src node ids)
__device__ int   g_blocksum[NB_SCAN];
__device__ int   g_blockoff[NB_SCAN];

// ---------------------------------------------------------------------------
// CSR build: counts -> scan -> fill
// ---------------------------------------------------------------------------
__global__ void cnt_init_kernel() {
    int i = blockIdx.x * blockDim.x + threadIdx.x;
    if (i < MN) g_cnt[i] = 0;
}

__global__ void count_kernel(const int* __restrict__ dst) {
    int e = blockIdx.x * blockDim.x + threadIdx.x;
    if (e < EE) {
        int d = dst[e];
        if ((unsigned)d < MN) atomicAdd(&g_cnt[d], 1);
    }
}

__global__ void scan_block_kernel() {
    __shared__ int s[256];
    int t = threadIdx.x;
    int i = blockIdx.x * 256 + t;
    int v = (i < MN) ? g_cnt[i] : 0;
    if (i < MN) g_dinv[i] = rsqrtf((float)v + 1.0f);
    s[t] = v;
    __syncthreads();
    for (int off = 128; off > 0; off >>= 1) {
        if (t < off) s[t] += s[t + off];
        __syncthreads();
    }
    if (t == 0) g_blocksum[blockIdx.x] = s[0];
}

__global__ void scan_top_kernel() {
    __shared__ int s[512];
    int t = threadIdx.x;
    int v = (t < NB_SCAN) ? g_blocksum[t] : 0;
    s[t] = v;
    __syncthreads();
    for (int off = 1; off < 512; off <<= 1) {
        int x = (t >= off) ? s[t - off] : 0;
        __syncthreads();
        s[t] += x;
        __syncthreads();
    }
    if (t < NB_SCAN) g_blockoff[t] = s[t] - v;        // exclusive
    if (t == 511)    g_rowptr[MN]  = s[511];          // total
}

__global__ void scan_apply_kernel() {
    __shared__ int s[256];
    int t = threadIdx.x;
    int i = blockIdx.x * 256 + t;
    int v = (i < MN) ? g_cnt[i] : 0;
    s[t] = v;
    __syncthreads();
    for (int off = 1; off < 256; off <<= 1) {
        int x = (t >= off) ? s[t - off] : 0;
        __syncthreads();
        s[t] += x;
        __syncthreads();
    }
    if (i < MN) {
        int rp = g_blockoff[blockIdx.x] + s[t] - v;   // exclusive prefix
        g_rowptr[i] = rp;
        g_cursor[i] = rp;
    }
}

__global__ void fill_kernel(const int* __restrict__ src, const int* __restrict__ dst) {
    int e = blockIdx.x * blockDim.x + threadIdx.x;
    if (e < EE) {
        int d = dst[e];
        int s = src[e];
        if ((unsigned)d < MN && (unsigned)s < MN) {
            int pos = atomicAdd(&g_cursor[d], 1);
            g_esrc[pos] = s;
        }
    }
}

// ---------------------------------------------------------------------------
// SGEMM (FFMA2 / f32x2 packed): g_g[r, :] = (A[r, :] @ W) * dinv[r]
// BM=128, BN=128 (= full H), BK=16, 256 threads.
// Per-thread 8 rows x 8 cols, accumulated as 8 x 4 f32x2 pairs.
// Ain == nullptr means "read from g_h".
// ---------------------------------------------------------------------------
__global__ void __launch_bounds__(256) gemm_scale_kernel(
    const float* __restrict__ Ain, const float* __restrict__ W, int K)
{
    const float* A = Ain ? Ain : g_h;

    __shared__ float As[16][128];   // [k][row]
    __shared__ float Bs[16][128];   // [k][col]

    const int tid  = threadIdx.x;
    const int row0 = blockIdx.x * 128;
    const int tx   = tid & 15;      // column group (8 cols)
    const int ty   = tid >> 4;      // row group (8 rows)

    unsigned long long acc[8][4];
#pragma unroll
    for (int i = 0; i < 8; i++)
#pragma unroll
        for (int p = 0; p < 4; p++) acc[i][p] = 0ULL;

    const int a_row = tid >> 1;            // 0..127
    const int a_kk0 = (tid & 1) * 8;       // 0 or 8
    const int nt = (K + 15) >> 4;

    for (int t = 0; t < nt; t++) {
        const int k0 = t * 16;

        // --- A tile: 128 rows x 16 k, scalar loads (K=133 rows misaligned) ---
        {
            int gr = row0 + a_row;
            const float* ap = A + (size_t)gr * K + k0 + a_kk0;
#pragma unroll
            for (int i = 0; i < 8; i++) {
                int gk = k0 + a_kk0 + i;
                float v = 0.f;
                if (gr < MN && gk < K) v = ap[i];
                As[a_kk0 + i][a_row] = v;
            }
        }
        // --- B tile: 16 k x 128 cols, float4 direct copy ---
        {
#pragma unroll
            for (int j = 0; j < 2; j++) {
                int idx  = tid + j * 256;        // 0..511 float4 slots
                int kk   = idx >> 5;
                int col4 = (idx & 31) * 4;
                int gk   = k0 + kk;
                float4 v = make_float4(0.f, 0.f, 0.f, 0.f);
                if (gk < K) v = *(const float4*)&W[(size_t)gk * HD + col4];
                *(float4*)&Bs[kk][col4] = v;
            }
        }
        __syncthreads();

#pragma unroll
        for (int k = 0; k < 16; k++) {
            const float4 a0 = *(const float4*)&As[k][ty * 8];
            const float4 a1 = *(const float4*)&As[k][ty * 8 + 4];
            const ulonglong2 bA = *(const ulonglong2*)&Bs[k][tx * 8];
            const ulonglong2 bB = *(const ulonglong2*)&Bs[k][tx * 8 + 4];
            unsigned long long bp0 = bA.x, bp1 = bA.y, bp2 = bB.x, bp3 = bB.y;
            float av[8];
            av[0]=a0.x; av[1]=a0.y; av[2]=a0.z; av[3]=a0.w;
            av[4]=a1.x; av[5]=a1.y; av[6]=a1.z; av[7]=a1.w;
#pragma unroll
            for (int i = 0; i < 8; i++) {
                unsigned long long ad;
                PACK_DUP(ad, av[i]);
                FFMA2(acc[i][0], ad, bp0);
                FFMA2(acc[i][1], ad, bp1);
                FFMA2(acc[i][2], ad, bp2);
                FFMA2(acc[i][3], ad, bp3);
            }
        }
        __syncthreads();
    }

    // --- epilogue: scale by dinv[row], store to g_g ---
#pragma unroll
    for (int i = 0; i < 8; i++) {
        int gr = row0 + ty * 8 + i;
        if (gr >= MN) continue;
        float di = g_dinv[gr];
        float c[8];
#pragma unroll
        for (int p = 0; p < 4; p++) {
            float lo, hi;
            UNPACK2(lo, hi, acc[i][p]);
            c[2 * p]     = lo * di;
            c[2 * p + 1] = hi * di;
        }
        float* pp = &g_g[(size_t)gr * HD + tx * 8];
        *(float4*)pp       = make_float4(c[0], c[1], c[2], c[3]);
        *(float4*)(pp + 4) = make_float4(c[4], c[5], c[6], c[7]);
    }
}

// ---------------------------------------------------------------------------
// Gather + finalize: one warp per dst node.
//   acc = g[i] + sum_{j in CSR row i} g[j];  dest[i] = tanh(dinv[i]*acc + b)
// dest == nullptr means "write to g_h".
// ---------------------------------------------------------------------------
__global__ void __launch_bounds__(256) gather_kernel(
    const float* __restrict__ b, float* __restrict__ dest_in)
{
    float* dest = dest_in ? dest_in : g_h;
    int warp = (blockIdx.x * blockDim.x + threadIdx.x) >> 5;
    int lane = threadIdx.x & 31;
    if (warp >= MN) return;
    const int i  = warp;
    const int c  = lane * 4;
    const int r0 = __ldg(&g_rowptr[i]);
    const int r1 = __ldg(&g_rowptr[i + 1]);

    // self term
    float4 acc = *(const float4*)&g_g[(size_t)i * HD + c];

    int e = r0;
    // 8-deep unroll for MLP against L2 latency
    for (; e + 8 <= r1; e += 8) {
        int s[8];
#pragma unroll
        for (int u = 0; u < 8; u++) s[u] = __ldg(&g_esrc[e + u]);
        float4 v[8];
#pragma unroll
        for (int u = 0; u < 8; u++)
            v[u] = *(const float4*)&g_g[(size_t)s[u] * HD + c];
#pragma unroll
        for (int u = 0; u < 8; u++) {
            acc.x += v[u].x; acc.y += v[u].y;
            acc.z += v[u].z; acc.w += v[u].w;
        }
    }
    for (; e < r1; e++) {
        int s = __ldg(&g_esrc[e]);
        float4 v = *(const float4*)&g_g[(size_t)s * HD + c];
        acc.x += v.x; acc.y += v.y; acc.z += v.z; acc.w += v.w;
    }

    float di = g_dinv[i];
    float4 bv = *(const float4*)&b[c];
    float4 o;
    o.x = tanhf(di * acc.x + bv.x);
    o.y = tanhf(di * acc.y + bv.y);
    o.z = tanhf(di * acc.z + bv.z);
    o.w = tanhf(di * acc.w + bv.w);
    *(float4*)&dest[(size_t)i * HD + c] = o;
}

// ---------------------------------------------------------------------------
// Launch
// ---------------------------------------------------------------------------
extern "C" void kernel_launch(void* const* d_in, const int* in_sizes, int n_in,
                              void* d_out, int out_size)
{
    const float* x  = (const float*)d_in[0];
    const int*   ei = (const int*)d_in[1];      // edge_index (int32 in harness)
    const float* W[4] = { (const float*)d_in[2], (const float*)d_in[4],
                          (const float*)d_in[6], (const float*)d_in[8] };
    const float* B[4] = { (const float*)d_in[3], (const float*)d_in[5],
                          (const float*)d_in[7], (const float*)d_in[9] };
    const int* src = ei;
    const int* dst = ei + EE;
    float* out = (float*)d_out;

    const int TPB = 256;
    const int nb_node = (MN + TPB - 1) / TPB;                 // 391
    const int nb_edge = (EE + TPB - 1) / TPB;                 // 6250
    const int nb_gemm = (MN + 127) / 128;                     // 782
    const int nb_gath = (int)(((long long)MN * 32 + TPB - 1) / TPB);  // 12500

    // CSR build (recomputed every launch; deterministic structure)
    cnt_init_kernel<<<nb_node, TPB>>>();
    count_kernel<<<nb_edge, TPB>>>(dst);
    scan_block_kernel<<<NB_SCAN, 256>>>();
    scan_top_kernel<<<1, 512>>>();
    scan_apply_kernel<<<NB_SCAN, 256>>>();
    fill_kernel<<<nb_edge, TPB>>>(src, dst);

    for (int l = 0; l < 4; l++) {
        const float* A = (l == 0) ? x : nullptr;   // nullptr -> g_h
        int K = (l == 0) ? NF : HD;
        float* dest = (l == 3) ? out : nullptr;    // nullptr -> g_h

        gemm_scale_kernel<<<nb_gemm, TPB>>>(A, W[l], K);
        gather_kernel<<<nb_gath, TPB>>>(B[l], dest);
    }
}

// round 8
// speedup vs baseline: 3.6233x; 1.0304x over previous
#include <cuda_runtime.h>
#include <cuda_bf16.h>
#include <math.h>

// Problem constants (fixed by the dataset)
#define MN 100000       // nodes
#define EE 1600000      // edges
#define NF 133          // input feature dim (layer 0 K)
#define HD 128          // hidden size
#define NB_SCAN ((MN + 255) / 256)   // 391 blocks in node-scan

// Packed f32x2 helpers (Blackwell FFMA2 — only reachable via PTX)
#define PACK_DUP(d, a)      asm("mov.b64 %0, {%1, %1};" : "=l"(d) : "f"(a))
#define UNPACK2(lo, hi, v)  asm("mov.b64 {%0, %1}, %2;" : "=f"(lo), "=f"(hi) : "l"(v))
#define FFMA2(d, a, b)      asm("fma.rn.f32x2 %0, %1, %2, %0;" : "+l"(d) : "l"(a), "l"(b))

// ---------------------------------------------------------------------------
// Static scratch (no allocations allowed anywhere)
// ---------------------------------------------------------------------------
__device__ float g_g[(size_t)MN * HD];     // g = h @ W  (unscaled)
__device__ float g_h[(size_t)MN * HD];     // inter-layer buffer
__device__ float g_dinv[MN];
__device__ int   g_cnt[MN];                // in-degree counts
__device__ int   g_rowptr[MN + 1];         // CSR row pointers (dst-indexed)
__device__ int   g_cursor[MN];             // fill cursors
__device__ int   g_esrc[EE];               // CSR column indices (src node ids)
__device__ int   g_blocksum[NB_SCAN];
__device__ int   g_blockoff[NB_SCAN];

// ---------------------------------------------------------------------------
// CSR build: counts -> scan -> fill   (runs on side stream, overlaps GEMM0)
// ---------------------------------------------------------------------------
__global__ void cnt_init_kernel() {
    int i = blockIdx.x * blockDim.x + threadIdx.x;
    if (i < MN) g_cnt[i] = 0;
}

__global__ void count_kernel(const int* __restrict__ dst) {
    int e = blockIdx.x * blockDim.x + threadIdx.x;
    if (e < EE) {
        int d = dst[e];
        if ((unsigned)d < MN) atomicAdd(&g_cnt[d], 1);
    }
}

__global__ void scan_block_kernel() {
    __shared__ int s[256];
    int t = threadIdx.x;
    int i = blockIdx.x * 256 + t;
    int v = (i < MN) ? g_cnt[i] : 0;
    if (i < MN) g_dinv[i] = rsqrtf((float)v + 1.0f);
    s[t] = v;
    __syncthreads();
    for (int off = 128; off > 0; off >>= 1) {
        if (t < off) s[t] += s[t + off];
        __syncthreads();
    }
    if (t == 0) g_blocksum[blockIdx.x] = s[0];
}

__global__ void scan_top_kernel() {
    __shared__ int s[512];
    int t = threadIdx.x;
    int v = (t < NB_SCAN) ? g_blocksum[t] : 0;
    s[t] = v;
    __syncthreads();
    for (int off = 1; off < 512; off <<= 1) {
        int x = (t >= off) ? s[t - off] : 0;
        __syncthreads();
        s[t] += x;
        __syncthreads();
    }
    if (t < NB_SCAN) g_blockoff[t] = s[t] - v;        // exclusive
    if (t == 511)    g_rowptr[MN]  = s[511];          // total
}

__global__ void scan_apply_kernel() {
    __shared__ int s[256];
    int t = threadIdx.x;
    int i = blockIdx.x * 256 + t;
    int v = (i < MN) ? g_cnt[i] : 0;
    s[t] = v;
    __syncthreads();
    for (int off = 1; off < 256; off <<= 1) {
        int x = (t >= off) ? s[t - off] : 0;
        __syncthreads();
        s[t] += x;
        __syncthreads();
    }
    if (i < MN) {
        int rp = g_blockoff[blockIdx.x] + s[t] - v;   // exclusive prefix
        g_rowptr[i] = rp;
        g_cursor[i] = rp;
    }
}

__global__ void fill_kernel(const int* __restrict__ src, const int* __restrict__ dst) {
    int e = blockIdx.x * blockDim.x + threadIdx.x;
    if (e < EE) {
        int d = dst[e];
        int s = src[e];
        if ((unsigned)d < MN && (unsigned)s < MN) {
            int pos = atomicAdd(&g_cursor[d], 1);
            g_esrc[pos] = s;
        }
    }
}

// ---------------------------------------------------------------------------
// SGEMM (FFMA2): g_g[r, :] = A[r, :] @ W   (no dinv — graph-independent)
// BM=128, BN=128, BK=16, 256 threads, per-thread 8x8 as 8x4 f32x2 pairs.
// Ain == nullptr means "read from g_h". K==128 path uses vectorized A loads.
// ---------------------------------------------------------------------------
__global__ void __launch_bounds__(256) gemm_kernel(
    const float* __restrict__ Ain, const float* __restrict__ W, int K)
{
    const float* A = Ain ? Ain : g_h;

    __shared__ float As[16][128];   // [k][row]
    __shared__ float Bs[16][128];   // [k][col]

    const int tid  = threadIdx.x;
    const int row0 = blockIdx.x * 128;
    const int tx   = tid & 15;      // column group (8 cols)
    const int ty   = tid >> 4;      // row group (8 rows)

    unsigned long long acc[8][4];
#pragma unroll
    for (int i = 0; i < 8; i++)
#pragma unroll
        for (int p = 0; p < 4; p++) acc[i][p] = 0ULL;

    const int a_row = tid >> 1;            // 0..127
    const int a_kk0 = (tid & 1) * 8;       // 0 or 8
    const int nt = (K + 15) >> 4;
    const bool k128 = (K == HD);

    for (int t = 0; t < nt; t++) {
        const int k0 = t * 16;

        // --- A tile: 128 rows x 16 k ---
        {
            int gr = row0 + a_row;
            if (k128) {
                // aligned: two float4 loads, no per-element guards
                float4 v0 = make_float4(0.f, 0.f, 0.f, 0.f);
                float4 v1 = v0;
                if (gr < MN) {
                    const float* ap = A + (size_t)gr * HD + k0 + a_kk0;
                    v0 = *(const float4*)ap;
                    v1 = *(const float4*)(ap + 4);
                }
                As[a_kk0 + 0][a_row] = v0.x;
                As[a_kk0 + 1][a_row] = v0.y;
                As[a_kk0 + 2][a_row] = v0.z;
                As[a_kk0 + 3][a_row] = v0.w;
                As[a_kk0 + 4][a_row] = v1.x;
                As[a_kk0 + 5][a_row] = v1.y;
                As[a_kk0 + 6][a_row] = v1.z;
                As[a_kk0 + 7][a_row] = v1.w;
            } else {
                const float* ap = A + (size_t)gr * K + k0 + a_kk0;
#pragma unroll
                for (int i = 0; i < 8; i++) {
                    int gk = k0 + a_kk0 + i;
                    float v = 0.f;
                    if (gr < MN && gk < K) v = ap[i];
                    As[a_kk0 + i][a_row] = v;
                }
            }
        }
        // --- B tile: 16 k x 128 cols, float4 direct copy ---
        {
#pragma unroll
            for (int j = 0; j < 2; j++) {
                int idx  = tid + j * 256;        // 0..511 float4 slots
                int kk   = idx >> 5;
                int col4 = (idx & 31) * 4;
                int gk   = k0 + kk;
                float4 v = make_float4(0.f, 0.f, 0.f, 0.f);
                if (gk < K) v = *(const float4*)&W[(size_t)gk * HD + col4];
                *(float4*)&Bs[kk][col4] = v;
            }
        }
        __syncthreads();

#pragma unroll
        for (int k = 0; k < 16; k++) {
            const float4 a0 = *(const float4*)&As[k][ty * 8];
            const float4 a1 = *(const float4*)&As[k][ty * 8 + 4];
            const ulonglong2 bA = *(const ulonglong2*)&Bs[k][tx * 8];
            const ulonglong2 bB = *(const ulonglong2*)&Bs[k][tx * 8 + 4];
            unsigned long long bp0 = bA.x, bp1 = bA.y, bp2 = bB.x, bp3 = bB.y;
            float av[8];
            av[0]=a0.x; av[1]=a0.y; av[2]=a0.z; av[3]=a0.w;
            av[4]=a1.x; av[5]=a1.y; av[6]=a1.z; av[7]=a1.w;
#pragma unroll
            for (int i = 0; i < 8; i++) {
                unsigned long long ad;
                PACK_DUP(ad, av[i]);
                FFMA2(acc[i][0], ad, bp0);
                FFMA2(acc[i][1], ad, bp1);
                FFMA2(acc[i][2], ad, bp2);
                FFMA2(acc[i][3], ad, bp3);
            }
        }
        __syncthreads();
    }

    // --- epilogue: store raw products to g_g ---
#pragma unroll
    for (int i = 0; i < 8; i++) {
        int gr = row0 + ty * 8 + i;
        if (gr >= MN) continue;
        float c[8];
#pragma unroll
        for (int p = 0; p < 4; p++) {
            float lo, hi;
            UNPACK2(lo, hi, acc[i][p]);
            c[2 * p]     = lo;
            c[2 * p + 1] = hi;
        }
        float* pp = &g_g[(size_t)gr * HD + tx * 8];
        *(float4*)pp       = make_float4(c[0], c[1], c[2], c[3]);
        *(float4*)(pp + 4) = make_float4(c[4], c[5], c[6], c[7]);
    }
}

// ---------------------------------------------------------------------------
// Gather + finalize: one warp per dst node.
//   acc = dinv[i]*g[i] + sum_{j in row i} dinv[s_j]*g[s_j]
//   dest[i] = tanh(dinv[i] * acc + b)
// dest == nullptr means "write to g_h".
// ---------------------------------------------------------------------------
__global__ void __launch_bounds__(256) gather_kernel(
    const float* __restrict__ b, float* __restrict__ dest_in)
{
    float* dest = dest_in ? dest_in : g_h;
    int warp = (blockIdx.x * blockDim.x + threadIdx.x) >> 5;
    int lane = threadIdx.x & 31;
    if (warp >= MN) return;
    const int i  = warp;
    const int c  = lane * 4;
    const int r0 = __ldg(&g_rowptr[i]);
    const int r1 = __ldg(&g_rowptr[i + 1]);
    const float di = g_dinv[i];

    // self term: dinv_i * g_i
    float4 gv = *(const float4*)&g_g[(size_t)i * HD + c];
    float4 acc;
    acc.x = di * gv.x; acc.y = di * gv.y;
    acc.z = di * gv.z; acc.w = di * gv.w;

    int e = r0;
    // 8-deep unroll for MLP against L2 latency
    for (; e + 8 <= r1; e += 8) {
        int s[8];
#pragma unroll
        for (int u = 0; u < 8; u++) s[u] = __ldg(&g_esrc[e + u]);
        float ds[8];
#pragma unroll
        for (int u = 0; u < 8; u++) ds[u] = __ldg(&g_dinv[s[u]]);  // warp-broadcast
        float4 v[8];
#pragma unroll
        for (int u = 0; u < 8; u++)
            v[u] = *(const float4*)&g_g[(size_t)s[u] * HD + c];
#pragma unroll
        for (int u = 0; u < 8; u++) {
            acc.x = fmaf(ds[u], v[u].x, acc.x);
            acc.y = fmaf(ds[u], v[u].y, acc.y);
            acc.z = fmaf(ds[u], v[u].z, acc.z);
            acc.w = fmaf(ds[u], v[u].w, acc.w);
        }
    }
    for (; e < r1; e++) {
        int s = __ldg(&g_esrc[e]);
        float dsv = __ldg(&g_dinv[s]);
        float4 v = *(const float4*)&g_g[(size_t)s * HD + c];
        acc.x = fmaf(dsv, v.x, acc.x);
        acc.y = fmaf(dsv, v.y, acc.y);
        acc.z = fmaf(dsv, v.z, acc.z);
        acc.w = fmaf(dsv, v.w, acc.w);
    }

    float4 bv = *(const float4*)&b[c];
    float4 o;
    o.x = tanhf(fmaf(di, acc.x, bv.x));
    o.y = tanhf(fmaf(di, acc.y, bv.y));
    o.z = tanhf(fmaf(di, acc.z, bv.z));
    o.w = tanhf(fmaf(di, acc.w, bv.w));
    *(float4*)&dest[(size_t)i * HD + c] = o;
}

// ---------------------------------------------------------------------------
// Launch: CSR build forked onto a side stream, overlapping layer-0 GEMM.
// ---------------------------------------------------------------------------
extern "C" void kernel_launch(void* const* d_in, const int* in_sizes, int n_in,
                              void* d_out, int out_size)
{
    const float* x  = (const float*)d_in[0];
    const int*   ei = (const int*)d_in[1];      // edge_index (int32 in harness)
    const float* W[4] = { (const float*)d_in[2], (const float*)d_in[4],
                          (const float*)d_in[6], (const float*)d_in[8] };
    const float* B[4] = { (const float*)d_in[3], (const float*)d_in[5],
                          (const float*)d_in[7], (const float*)d_in[9] };
    const int* src = ei;
    const int* dst = ei + EE;
    float* out = (float*)d_out;

    const int TPB = 256;
    const int nb_node = (MN + TPB - 1) / TPB;                 // 391
    const int nb_edge = (EE + TPB - 1) / TPB;                 // 6250
    const int nb_gemm = (MN + 127) / 128;                     // 782
    const int nb_gath = (int)(((long long)MN * 32 + TPB - 1) / TPB);  // 12500

    // side stream + fork/join events (created per call; kernel_launch runs
    // host-side only twice — correctness + capture — so no resource growth)
    cudaStream_t s2;
    cudaEvent_t  eFork, eJoin;
    cudaStreamCreateWithFlags(&s2, cudaStreamNonBlocking);
    cudaEventCreateWithFlags(&eFork, cudaEventDisableTiming);
    cudaEventCreateWithFlags(&eJoin, cudaEventDisableTiming);

    // fork: CSR build on s2 (graph-independent GEMM0 runs concurrently)
    cudaEventRecord(eFork, 0);
    cudaStreamWaitEvent(s2, eFork, 0);
    cnt_init_kernel<<<nb_node, TPB, 0, s2>>>();
    count_kernel<<<nb_edge, TPB, 0, s2>>>(dst);
    scan_block_kernel<<<NB_SCAN, 256, 0, s2>>>();
    scan_top_kernel<<<1, 512, 0, s2>>>();
    scan_apply_kernel<<<NB_SCAN, 256, 0, s2>>>();
    fill_kernel<<<nb_edge, TPB, 0, s2>>>(src, dst);
    cudaEventRecord(eJoin, s2);

    // main stream: layer-0 GEMM overlaps the CSR build
    gemm_kernel<<<nb_gemm, TPB>>>(x, W[0], NF);
    cudaStreamWaitEvent(0, eJoin, 0);
    gather_kernel<<<nb_gath, TPB>>>(B[0], nullptr);

    for (int l = 1; l < 4; l++) {
        float* dest = (l == 3) ? out : nullptr;    // nullptr -> g_h
        gemm_kernel<<<nb_gemm, TPB>>>(nullptr, W[l], HD);
        gather_kernel<<<nb_gath, TPB>>>(B[l], dest);
    }
}

// round 10
// speedup vs baseline: 3.7528x; 1.0357x over previous
#include <cuda_runtime.h>
#include <cuda_bf16.h>
#include <math.h>

// Problem constants (fixed by the dataset)
#define MN 100000       // nodes
#define EE 1600000      // edges
#define NF 133          // input feature dim (layer 0 K)
#define HD 128          // hidden size
#define NB_SCAN ((MN + 255) / 256)   // 391 blocks in node-scan

// Packed f32x2 helpers (Blackwell FFMA2 — only reachable via PTX)
#define PACK_DUP(d, a)      asm("mov.b64 %0, {%1, %1};" : "=l"(d) : "f"(a))
#define UNPACK2(lo, hi, v)  asm("mov.b64 {%0, %1}, %2;" : "=f"(lo), "=f"(hi) : "l"(v))
#define FFMA2(d, a, b)      asm("fma.rn.f32x2 %0, %1, %2, %0;" : "+l"(d) : "l"(a), "l"(b))

// ---------------------------------------------------------------------------
// Static scratch (no allocations allowed anywhere)
// ---------------------------------------------------------------------------
__device__ float g_g[(size_t)MN * HD];     // g = h @ W  (unscaled)
__device__ float g_h[(size_t)MN * HD];     // inter-layer buffer
__device__ float g_dinv[MN];
__device__ int   g_cnt[MN];                // in-degree counts
__device__ int   g_rowptr[MN + 1];         // CSR row pointers (dst-indexed)
__device__ int   g_cursor[MN];             // fill cursors
__device__ int   g_esrc[EE];               // CSR column indices (src node ids)
__device__ int   g_blocksum[NB_SCAN];
__device__ int   g_blockoff[NB_SCAN];

// ---------------------------------------------------------------------------
// CSR build: counts -> scan -> fill   (runs on side stream, overlaps GEMM0)
// ---------------------------------------------------------------------------
__global__ void cnt_init_kernel() {
    int i = blockIdx.x * blockDim.x + threadIdx.x;
    if (i < MN) g_cnt[i] = 0;
}

__global__ void count_kernel(const int* __restrict__ dst) {
    int e = blockIdx.x * blockDim.x + threadIdx.x;
    if (e < EE) {
        int d = dst[e];
        if ((unsigned)d < MN) atomicAdd(&g_cnt[d], 1);
    }
}

__global__ void scan_block_kernel() {
    __shared__ int s[256];
    int t = threadIdx.x;
    int i = blockIdx.x * 256 + t;
    int v = (i < MN) ? g_cnt[i] : 0;
    if (i < MN) g_dinv[i] = rsqrtf((float)v + 1.0f);
    s[t] = v;
    __syncthreads();
    for (int off = 128; off > 0; off >>= 1) {
        if (t < off) s[t] += s[t + off];
        __syncthreads();
    }
    if (t == 0) g_blocksum[blockIdx.x] = s[0];
}

__global__ void scan_top_kernel() {
    __shared__ int s[512];
    int t = threadIdx.x;
    int v = (t < NB_SCAN) ? g_blocksum[t] : 0;
    s[t] = v;
    __syncthreads();
    for (int off = 1; off < 512; off <<= 1) {
        int x = (t >= off) ? s[t - off] : 0;
        __syncthreads();
        s[t] += x;
        __syncthreads();
    }
    if (t < NB_SCAN) g_blockoff[t] = s[t] - v;        // exclusive
    if (t == 511)    g_rowptr[MN]  = s[511];          // total
}

__global__ void scan_apply_kernel() {
    __shared__ int s[256];
    int t = threadIdx.x;
    int i = blockIdx.x * 256 + t;
    int v = (i < MN) ? g_cnt[i] : 0;
    s[t] = v;
    __syncthreads();
    for (int off = 1; off < 256; off <<= 1) {
        int x = (t >= off) ? s[t - off] : 0;
        __syncthreads();
        s[t] += x;
        __syncthreads();
    }
    if (i < MN) {
        int rp = g_blockoff[blockIdx.x] + s[t] - v;   // exclusive prefix
        g_rowptr[i] = rp;
        g_cursor[i] = rp;
    }
}

__global__ void fill_kernel(const int* __restrict__ src, const int* __restrict__ dst) {
    int e = blockIdx.x * blockDim.x + threadIdx.x;
    if (e < EE) {
        int d = dst[e];
        int s = src[e];
        if ((unsigned)d < MN && (unsigned)s < MN) {
            int pos = atomicAdd(&g_cursor[d], 1);
            g_esrc[pos] = s;
        }
    }
}

// ---------------------------------------------------------------------------
// SGEMM (FFMA2, register-prefetch pipeline): g_g[r,:] = A[r,:] @ W
// BM=128, BN=128, BK=16, 256 threads, per-thread 8x8 as 8x4 f32x2 pairs.
// Ain == nullptr means "read from g_h". K==128 path uses vectorized A loads.
// ---------------------------------------------------------------------------
__global__ void __launch_bounds__(256) gemm_kernel(
    const float* __restrict__ Ain, const float* __restrict__ W, int K)
{
    const float* A = Ain ? Ain : g_h;

    __shared__ float As[16][128];   // [k][row]
    __shared__ float Bs[16][128];   // [k][col]

    const int tid  = threadIdx.x;
    const int row0 = blockIdx.x * 128;
    const int tx   = tid & 15;      // column group (8 cols)
    const int ty   = tid >> 4;      // row group (8 rows)

    unsigned long long acc[8][4];
#pragma unroll
    for (int i = 0; i < 8; i++)
#pragma unroll
        for (int p = 0; p < 4; p++) acc[i][p] = 0ULL;

    const int a_row = tid >> 1;            // 0..127
    const int a_kk0 = (tid & 1) * 8;       // 0 or 8
    const int b_kk  = tid >> 5;            // 0..7   (row of first B float4)
    const int b_c4  = (tid & 31) * 4;      // column (float4 aligned)
    const int nt = (K + 15) >> 4;
    const bool k128 = (K == HD);
    const int gr = row0 + a_row;

    float  aR[8];                          // prefetch regs: A fragment
    float4 bR0, bR1;                       // prefetch regs: B fragments

    // ---- prefetch tile 0 into regs ----
    auto loadTile = [&](int t) {
        const int k0 = t * 16;
        if (k128) {
            float4 v0 = make_float4(0.f, 0.f, 0.f, 0.f), v1 = v0;
            if (gr < MN) {
                const float* ap = A + (size_t)gr * HD + k0 + a_kk0;
                v0 = *(const float4*)ap;
                v1 = *(const float4*)(ap + 4);
            }
            aR[0]=v0.x; aR[1]=v0.y; aR[2]=v0.z; aR[3]=v0.w;
            aR[4]=v1.x; aR[5]=v1.y; aR[6]=v1.z; aR[7]=v1.w;
        } else {
            const float* ap = A + (size_t)gr * K + k0 + a_kk0;
#pragma unroll
            for (int i = 0; i < 8; i++) {
                int gk = k0 + a_kk0 + i;
                aR[i] = (gr < MN && gk < K) ? ap[i] : 0.f;
            }
        }
        int gk0 = k0 + b_kk;
        int gk1 = k0 + b_kk + 8;
        bR0 = make_float4(0.f, 0.f, 0.f, 0.f);
        bR1 = bR0;
        if (gk0 < K) bR0 = *(const float4*)&W[(size_t)gk0 * HD + b_c4];
        if (gk1 < K) bR1 = *(const float4*)&W[(size_t)gk1 * HD + b_c4];
    };
    auto storeTile = [&]() {
#pragma unroll
        for (int i = 0; i < 8; i++) As[a_kk0 + i][a_row] = aR[i];
        *(float4*)&Bs[b_kk][b_c4]     = bR0;
        *(float4*)&Bs[b_kk + 8][b_c4] = bR1;
    };

    loadTile(0);
    storeTile();
    __syncthreads();

    for (int t = 0; t < nt; t++) {
        // issue next tile's LDGs before compute (latency hidden under FFMA2)
        if (t + 1 < nt) loadTile(t + 1);

#pragma unroll
        for (int k = 0; k < 16; k++) {
            const float4 a0 = *(const float4*)&As[k][ty * 8];
            const float4 a1 = *(const float4*)&As[k][ty * 8 + 4];
            const ulonglong2 bA = *(const ulonglong2*)&Bs[k][tx * 8];
            const ulonglong2 bB = *(const ulonglong2*)&Bs[k][tx * 8 + 4];
            unsigned long long bp0 = bA.x, bp1 = bA.y, bp2 = bB.x, bp3 = bB.y;
            float av[8];
            av[0]=a0.x; av[1]=a0.y; av[2]=a0.z; av[3]=a0.w;
            av[4]=a1.x; av[5]=a1.y; av[6]=a1.z; av[7]=a1.w;
#pragma unroll
            for (int i = 0; i < 8; i++) {
                unsigned long long ad;
                PACK_DUP(ad, av[i]);
                FFMA2(acc[i][0], ad, bp0);
                FFMA2(acc[i][1], ad, bp1);
                FFMA2(acc[i][2], ad, bp2);
                FFMA2(acc[i][3], ad, bp3);
            }
        }
        __syncthreads();
        if (t + 1 < nt) {
            storeTile();
            __syncthreads();
        }
    }

    // --- epilogue: store raw products to g_g ---
#pragma unroll
    for (int i = 0; i < 8; i++) {
        int r = row0 + ty * 8 + i;
        if (r >= MN) continue;
        float c[8];
#pragma unroll
        for (int p = 0; p < 4; p++) {
            float lo, hi;
            UNPACK2(lo, hi, acc[i][p]);
            c[2 * p]     = lo;
            c[2 * p + 1] = hi;
        }
        float* pp = &g_g[(size_t)r * HD + tx * 8];
        *(float4*)pp       = make_float4(c[0], c[1], c[2], c[3]);
        *(float4*)(pp + 4) = make_float4(c[4], c[5], c[6], c[7]);
    }
}

// ---------------------------------------------------------------------------
// Gather + finalize: one warp per dst node.
//   acc = dinv[i]*g[i] + sum_{j in row i} dinv[s_j]*g[s_j]
//   dest[i] = tanh(dinv[i] * acc + b)
// dest == nullptr means "write to g_h".
// ---------------------------------------------------------------------------
__global__ void __launch_bounds__(256) gather_kernel(
    const float* __restrict__ b, float* __restrict__ dest_in)
{
    float* dest = dest_in ? dest_in : g_h;
    int warp = (blockIdx.x * blockDim.x + threadIdx.x) >> 5;
    int lane = threadIdx.x & 31;
    if (warp >= MN) return;
    const int i  = warp;
    const int c  = lane * 4;
    const int r0 = __ldg(&g_rowptr[i]);
    const int r1 = __ldg(&g_rowptr[i + 1]);
    const float di = g_dinv[i];

    // self term: dinv_i * g_i
    float4 gv = *(const float4*)&g_g[(size_t)i * HD + c];
    float4 acc;
    acc.x = di * gv.x; acc.y = di * gv.y;
    acc.z = di * gv.z; acc.w = di * gv.w;

    int e = r0;
    // 8-deep unroll for MLP against L2 latency
    for (; e + 8 <= r1; e += 8) {
        int s[8];
#pragma unroll
        for (int u = 0; u < 8; u++) s[u] = __ldg(&g_esrc[e + u]);
        float ds[8];
#pragma unroll
        for (int u = 0; u < 8; u++) ds[u] = __ldg(&g_dinv[s[u]]);  // warp-broadcast
        float4 v[8];
#pragma unroll
        for (int u = 0; u < 8; u++)
            v[u] = *(const float4*)&g_g[(size_t)s[u] * HD + c];
#pragma unroll
        for (int u = 0; u < 8; u++) {
            acc.x = fmaf(ds[u], v[u].x, acc.x);
            acc.y = fmaf(ds[u], v[u].y, acc.y);
            acc.z = fmaf(ds[u], v[u].z, acc.z);
            acc.w = fmaf(ds[u], v[u].w, acc.w);
        }
    }
    for (; e < r1; e++) {
        int s = __ldg(&g_esrc[e]);
        float dsv = __ldg(&g_dinv[s]);
        float4 v = *(const float4*)&g_g[(size_t)s * HD + c];
        acc.x = fmaf(dsv, v.x, acc.x);
        acc.y = fmaf(dsv, v.y, acc.y);
        acc.z = fmaf(dsv, v.z, acc.z);
        acc.w = fmaf(dsv, v.w, acc.w);
    }

    float4 bv = *(const float4*)&b[c];
    float4 o;
    o.x = tanhf(fmaf(di, acc.x, bv.x));
    o.y = tanhf(fmaf(di, acc.y, bv.y));
    o.z = tanhf(fmaf(di, acc.z, bv.z));
    o.w = tanhf(fmaf(di, acc.w, bv.w));
    *(float4*)&dest[(size_t)i * HD + c] = o;
}

// ---------------------------------------------------------------------------
// Launch: CSR build forked onto one side stream, overlapping layer-0 GEMM.
// (R8 topology — the chunked pipeline measured slower and is dropped.)
// ---------------------------------------------------------------------------
extern "C" void kernel_launch(void* const* d_in, const int* in_sizes, int n_in,
                              void* d_out, int out_size)
{
    const float* x  = (const float*)d_in[0];
    const int*   ei = (const int*)d_in[1];      // edge_index (int32 in harness)
    const float* W[4] = { (const float*)d_in[2], (const float*)d_in[4],
                          (const float*)d_in[6], (const float*)d_in[8] };
    const float* B[4] = { (const float*)d_in[3], (const float*)d_in[5],
                          (const float*)d_in[7], (const float*)d_in[9] };
    const int* src = ei;
    const int* dst = ei + EE;
    float* out = (float*)d_out;

    const int TPB = 256;
    const int nb_node = (MN + TPB - 1) / TPB;                 // 391
    const int nb_edge = (EE + TPB - 1) / TPB;                 // 6250
    const int nb_gemm = (MN + 127) / 128;                     // 782
    const int nb_gath = (int)(((long long)MN * 32 + TPB - 1) / TPB);  // 12500

    // Are we inside graph capture? (identical device work either way; only
    // host-side resource cleanup differs — destroying streams/events mid-
    // capture would invalidate the capture, so we skip it there.)
    cudaStreamCaptureStatus cap = cudaStreamCaptureStatusNone;
    cudaStreamIsCapturing(0, &cap);

    cudaStream_t s2;
    cudaEvent_t  eFork, eJoin;
    cudaStreamCreateWithFlags(&s2, cudaStreamNonBlocking);
    cudaEventCreateWithFlags(&eFork, cudaEventDisableTiming);
    cudaEventCreateWithFlags(&eJoin, cudaEventDisableTiming);

    // fork: CSR build on s2 (graph-independent GEMM0 runs concurrently)
    cudaEventRecord(eFork, 0);
    cudaStreamWaitEvent(s2, eFork, 0);
    cnt_init_kernel<<<nb_node, TPB, 0, s2>>>();
    count_kernel<<<nb_edge, TPB, 0, s2>>>(dst);
    scan_block_kernel<<<NB_SCAN, 256, 0, s2>>>();
    scan_top_kernel<<<1, 512, 0, s2>>>();
    scan_apply_kernel<<<NB_SCAN, 256, 0, s2>>>();
    fill_kernel<<<nb_edge, TPB, 0, s2>>>(src, dst);
    cudaEventRecord(eJoin, s2);

    // main stream: layer-0 GEMM overlaps the CSR build
    gemm_kernel<<<nb_gemm, TPB>>>(x, W[0], NF);
    cudaStreamWaitEvent(0, eJoin, 0);
    gather_kernel<<<nb_gath, TPB>>>(B[0], nullptr);

    for (int l = 1; l < 4; l++) {
        float* dest = (l == 3) ? out : nullptr;    // nullptr -> g_h
        gemm_kernel<<<nb_gemm, TPB>>>(nullptr, W[l], HD);
        gather_kernel<<<nb_gath, TPB>>>(B[l], dest);
    }

    // cleanup outside capture (destruction is deferred until queued work drains)
    if (cap == cudaStreamCaptureStatusNone) {
        cudaEventDestroy(eFork);
        cudaEventDestroy(eJoin);
        cudaStreamDestroy(s2);
    }
}

// round 11
// speedup vs baseline: 4.1219x; 1.0984x over previous
#include <cuda_runtime.h>
#include <cuda_fp16.h>
#include <cuda_bf16.h>
#include <math.h>

// Problem constants (fixed by the dataset)
#define MN 100000       // nodes
#define EE 1600000      // edges
#define NF 133          // input feature dim (layer 0 K)
#define HD 128          // hidden size
#define NB_SCAN ((MN + 255) / 256)   // 391 blocks in node-scan

// Packed f32x2 helpers (Blackwell FFMA2 — only reachable via PTX)
#define PACK_DUP(d, a)      asm("mov.b64 %0, {%1, %1};" : "=l"(d) : "f"(a))
#define UNPACK2(lo, hi, v)  asm("mov.b64 {%0, %1}, %2;" : "=f"(lo), "=f"(hi) : "l"(v))
#define FFMA2(d, a, b)      asm("fma.rn.f32x2 %0, %1, %2, %0;" : "+l"(d) : "l"(a), "l"(b))

// ---------------------------------------------------------------------------
// Static scratch (no allocations allowed anywhere)
// ---------------------------------------------------------------------------
__device__ __half g_gh[(size_t)MN * HD];   // g = h @ W, stored fp16 (gather payload)
__device__ float  g_h[(size_t)MN * HD];    // inter-layer buffer (fp32)
__device__ float  g_dinv[MN];
__device__ int    g_cnt[MN];               // in-degree counts
__device__ int    g_rowptr[MN + 1];        // CSR row pointers (dst-indexed)
__device__ int    g_cursor[MN];            // fill cursors
__device__ int    g_esrc[EE];              // CSR column indices (src node ids)
__device__ int    g_blocksum[NB_SCAN];
__device__ int    g_blockoff[NB_SCAN];

// ---------------------------------------------------------------------------
// CSR build: counts -> scan -> fill   (runs on side stream, overlaps GEMM0)
// ---------------------------------------------------------------------------
__global__ void cnt_init_kernel() {
    int i = blockIdx.x * blockDim.x + threadIdx.x;
    if (i < MN) g_cnt[i] = 0;
}

__global__ void count_kernel(const int* __restrict__ dst) {
    int e = blockIdx.x * blockDim.x + threadIdx.x;
    if (e < EE) {
        int d = dst[e];
        if ((unsigned)d < MN) atomicAdd(&g_cnt[d], 1);
    }
}

__global__ void scan_block_kernel() {
    __shared__ int s[256];
    int t = threadIdx.x;
    int i = blockIdx.x * 256 + t;
    int v = (i < MN) ? g_cnt[i] : 0;
    if (i < MN) g_dinv[i] = rsqrtf((float)v + 1.0f);
    s[t] = v;
    __syncthreads();
    for (int off = 128; off > 0; off >>= 1) {
        if (t < off) s[t] += s[t + off];
        __syncthreads();
    }
    if (t == 0) g_blocksum[blockIdx.x] = s[0];
}

__global__ void scan_top_kernel() {
    __shared__ int s[512];
    int t = threadIdx.x;
    int v = (t < NB_SCAN) ? g_blocksum[t] : 0;
    s[t] = v;
    __syncthreads();
    for (int off = 1; off < 512; off <<= 1) {
        int x = (t >= off) ? s[t - off] : 0;
        __syncthreads();
        s[t] += x;
        __syncthreads();
    }
    if (t < NB_SCAN) g_blockoff[t] = s[t] - v;        // exclusive
    if (t == 511)    g_rowptr[MN]  = s[511];          // total
}

__global__ void scan_apply_kernel() {
    __shared__ int s[256];
    int t = threadIdx.x;
    int i = blockIdx.x * 256 + t;
    int v = (i < MN) ? g_cnt[i] : 0;
    s[t] = v;
    __syncthreads();
    for (int off = 1; off < 256; off <<= 1) {
        int x = (t >= off) ? s[t - off] : 0;
        __syncthreads();
        s[t] += x;
        __syncthreads();
    }
    if (i < MN) {
        int rp = g_blockoff[blockIdx.x] + s[t] - v;   // exclusive prefix
        g_rowptr[i] = rp;
        g_cursor[i] = rp;
    }
}

__global__ void fill_kernel(const int* __restrict__ src, const int* __restrict__ dst) {
    int e = blockIdx.x * blockDim.x + threadIdx.x;
    if (e < EE) {
        int d = dst[e];
        int s = src[e];
        if ((unsigned)d < MN && (unsigned)s < MN) {
            int pos = atomicAdd(&g_cursor[d], 1);
            g_esrc[pos] = s;
        }
    }
}

// ---------------------------------------------------------------------------
// SGEMM (FFMA2, register-prefetch pipeline): g_gh[r,:] = fp16(A[r,:] @ W)
// Compute fully fp32; rounds to fp16 only at the epilogue store.
// BM=128, BN=128, BK=16, 256 threads, per-thread 8x8 as 8x4 f32x2 pairs.
// Ain == nullptr means "read from g_h". K==128 path uses vectorized A loads.
// ---------------------------------------------------------------------------
__global__ void __launch_bounds__(256) gemm_kernel(
    const float* __restrict__ Ain, const float* __restrict__ W, int K)
{
    const float* A = Ain ? Ain : g_h;

    __shared__ float As[16][128];   // [k][row]
    __shared__ float Bs[16][128];   // [k][col]

    const int tid  = threadIdx.x;
    const int row0 = blockIdx.x * 128;
    const int tx   = tid & 15;      // column group (8 cols)
    const int ty   = tid >> 4;      // row group (8 rows)

    unsigned long long acc[8][4];
#pragma unroll
    for (int i = 0; i < 8; i++)
#pragma unroll
        for (int p = 0; p < 4; p++) acc[i][p] = 0ULL;

    const int a_row = tid >> 1;            // 0..127
    const int a_kk0 = (tid & 1) * 8;       // 0 or 8
    const int b_kk  = tid >> 5;            // 0..7   (row of first B float4)
    const int b_c4  = (tid & 31) * 4;      // column (float4 aligned)
    const int nt = (K + 15) >> 4;
    const bool k128 = (K == HD);
    const int gr = row0 + a_row;

    float  aR[8];                          // prefetch regs: A fragment
    float4 bR0, bR1;                       // prefetch regs: B fragments

    auto loadTile = [&](int t) {
        const int k0 = t * 16;
        if (k128) {
            float4 v0 = make_float4(0.f, 0.f, 0.f, 0.f), v1 = v0;
            if (gr < MN) {
                const float* ap = A + (size_t)gr * HD + k0 + a_kk0;
                v0 = *(const float4*)ap;
                v1 = *(const float4*)(ap + 4);
            }
            aR[0]=v0.x; aR[1]=v0.y; aR[2]=v0.z; aR[3]=v0.w;
            aR[4]=v1.x; aR[5]=v1.y; aR[6]=v1.z; aR[7]=v1.w;
        } else {
            const float* ap = A + (size_t)gr * K + k0 + a_kk0;
#pragma unroll
            for (int i = 0; i < 8; i++) {
                int gk = k0 + a_kk0 + i;
                aR[i] = (gr < MN && gk < K) ? ap[i] : 0.f;
            }
        }
        int gk0 = k0 + b_kk;
        int gk1 = k0 + b_kk + 8;
        bR0 = make_float4(0.f, 0.f, 0.f, 0.f);
        bR1 = bR0;
        if (gk0 < K) bR0 = *(const float4*)&W[(size_t)gk0 * HD + b_c4];
        if (gk1 < K) bR1 = *(const float4*)&W[(size_t)gk1 * HD + b_c4];
    };
    auto storeTile = [&]() {
#pragma unroll
        for (int i = 0; i < 8; i++) As[a_kk0 + i][a_row] = aR[i];
        *(float4*)&Bs[b_kk][b_c4]     = bR0;
        *(float4*)&Bs[b_kk + 8][b_c4] = bR1;
    };

    loadTile(0);
    storeTile();
    __syncthreads();

    for (int t = 0; t < nt; t++) {
        // issue next tile's LDGs before compute (latency hidden under FFMA2)
        if (t + 1 < nt) loadTile(t + 1);

#pragma unroll
        for (int k = 0; k < 16; k++) {
            const float4 a0 = *(const float4*)&As[k][ty * 8];
            const float4 a1 = *(const float4*)&As[k][ty * 8 + 4];
            const ulonglong2 bA = *(const ulonglong2*)&Bs[k][tx * 8];
            const ulonglong2 bB = *(const ulonglong2*)&Bs[k][tx * 8 + 4];
            unsigned long long bp0 = bA.x, bp1 = bA.y, bp2 = bB.x, bp3 = bB.y;
            float av[8];
            av[0]=a0.x; av[1]=a0.y; av[2]=a0.z; av[3]=a0.w;
            av[4]=a1.x; av[5]=a1.y; av[6]=a1.z; av[7]=a1.w;
#pragma unroll
            for (int i = 0; i < 8; i++) {
                unsigned long long ad;
                PACK_DUP(ad, av[i]);
                FFMA2(acc[i][0], ad, bp0);
                FFMA2(acc[i][1], ad, bp1);
                FFMA2(acc[i][2], ad, bp2);
                FFMA2(acc[i][3], ad, bp3);
            }
        }
        __syncthreads();
        if (t + 1 < nt) {
            storeTile();
            __syncthreads();
        }
    }

    // --- epilogue: round to fp16, store 8 halves (one uint4) ---
#pragma unroll
    for (int i = 0; i < 8; i++) {
        int r = row0 + ty * 8 + i;
        if (r >= MN) continue;
        __half2 hp[4];
#pragma unroll
        for (int p = 0; p < 4; p++) {
            float lo, hi;
            UNPACK2(lo, hi, acc[i][p]);
            hp[p] = __floats2half2_rn(lo, hi);
        }
        // tx*8 halves = tx*16 bytes -> 16B aligned
        *(uint4*)&g_gh[(size_t)r * HD + tx * 8] = *(uint4*)hp;
    }
}

// ---------------------------------------------------------------------------
// Gather + finalize: one warp per dst node; g payload is fp16, accum fp32.
//   acc = dinv[i]*g[i] + sum_{j in row i} dinv[s_j]*g[s_j]
//   dest[i] = tanh(dinv[i] * acc + b)
// dest == nullptr means "write to g_h".
// ---------------------------------------------------------------------------
__global__ void __launch_bounds__(256) gather_kernel(
    const float* __restrict__ b, float* __restrict__ dest_in)
{
    float* dest = dest_in ? dest_in : g_h;
    int warp = (blockIdx.x * blockDim.x + threadIdx.x) >> 5;
    int lane = threadIdx.x & 31;
    if (warp >= MN) return;
    const int i  = warp;
    const int c  = lane * 4;                // 4 features per lane
    const int r0 = __ldg(&g_rowptr[i]);
    const int r1 = __ldg(&g_rowptr[i + 1]);
    const float di = g_dinv[i];

    // self term: dinv_i * g_i   (uint2 = 4 halves = 8 B per lane)
    uint2 sr = *(const uint2*)&g_gh[(size_t)i * HD + c];
    float2 s01 = __half22float2(*(__half2*)&sr.x);
    float2 s23 = __half22float2(*(__half2*)&sr.y);
    float4 acc;
    acc.x = di * s01.x; acc.y = di * s01.y;
    acc.z = di * s23.x; acc.w = di * s23.y;

    int e = r0;
    // 8-deep unroll for MLP against L2 latency
    for (; e + 8 <= r1; e += 8) {
        int s[8];
#pragma unroll
        for (int u = 0; u < 8; u++) s[u] = __ldg(&g_esrc[e + u]);
        float ds[8];
#pragma unroll
        for (int u = 0; u < 8; u++) ds[u] = __ldg(&g_dinv[s[u]]);  // warp-broadcast
        uint2 v[8];
#pragma unroll
        for (int u = 0; u < 8; u++)
            v[u] = *(const uint2*)&g_gh[(size_t)s[u] * HD + c];
#pragma unroll
        for (int u = 0; u < 8; u++) {
            float2 f01 = __half22float2(*(__half2*)&v[u].x);
            float2 f23 = __half22float2(*(__half2*)&v[u].y);
            acc.x = fmaf(ds[u], f01.x, acc.x);
            acc.y = fmaf(ds[u], f01.y, acc.y);
            acc.z = fmaf(ds[u], f23.x, acc.z);
            acc.w = fmaf(ds[u], f23.y, acc.w);
        }
    }
    for (; e < r1; e++) {
        int s = __ldg(&g_esrc[e]);
        float dsv = __ldg(&g_dinv[s]);
        uint2 v = *(const uint2*)&g_gh[(size_t)s * HD + c];
        float2 f01 = __half22float2(*(__half2*)&v.x);
        float2 f23 = __half22float2(*(__half2*)&v.y);
        acc.x = fmaf(dsv, f01.x, acc.x);
        acc.y = fmaf(dsv, f01.y, acc.y);
        acc.z = fmaf(dsv, f23.x, acc.z);
        acc.w = fmaf(dsv, f23.y, acc.w);
    }

    float4 bv = *(const float4*)&b[c];
    float4 o;
    o.x = tanhf(fmaf(di, acc.x, bv.x));
    o.y = tanhf(fmaf(di, acc.y, bv.y));
    o.z = tanhf(fmaf(di, acc.z, bv.z));
    o.w = tanhf(fmaf(di, acc.w, bv.w));
    *(float4*)&dest[(size_t)i * HD + c] = o;
}

// ---------------------------------------------------------------------------
// Launch: CSR build forked onto one side stream, overlapping layer-0 GEMM.
// ---------------------------------------------------------------------------
extern "C" void kernel_launch(void* const* d_in, const int* in_sizes, int n_in,
                              void* d_out, int out_size)
{
    const float* x  = (const float*)d_in[0];
    const int*   ei = (const int*)d_in[1];      // edge_index (int32 in harness)
    const float* W[4] = { (const float*)d_in[2], (const float*)d_in[4],
                          (const float*)d_in[6], (const float*)d_in[8] };
    const float* B[4] = { (const float*)d_in[3], (const float*)d_in[5],
                          (const float*)d_in[7], (const float*)d_in[9] };
    const int* src = ei;
    const int* dst = ei + EE;
    float* out = (float*)d_out;

    const int TPB = 256;
    const int nb_node = (MN + TPB - 1) / TPB;                 // 391
    const int nb_edge = (EE + TPB - 1) / TPB;                 // 6250
    const int nb_gemm = (MN + 127) / 128;                     // 782
    const int nb_gath = (int)(((long long)MN * 32 + TPB - 1) / TPB);  // 12500

    // Capture-aware resource hygiene (identical device work on every call)
    cudaStreamCaptureStatus cap = cudaStreamCaptureStatusNone;
    cudaStreamIsCapturing(0, &cap);

    cudaStream_t s2;
    cudaEvent_t  eFork, eJoin;
    cudaStreamCreateWithFlags(&s2, cudaStreamNonBlocking);
    cudaEventCreateWithFlags(&eFork, cudaEventDisableTiming);
    cudaEventCreateWithFlags(&eJoin, cudaEventDisableTiming);

    // fork: CSR build on s2 (graph-independent GEMM0 runs concurrently)
    cudaEventRecord(eFork, 0);
    cudaStreamWaitEvent(s2, eFork, 0);
    cnt_init_kernel<<<nb_node, TPB, 0, s2>>>();
    count_kernel<<<nb_edge, TPB, 0, s2>>>(dst);
    scan_block_kernel<<<NB_SCAN, 256, 0, s2>>>();
    scan_top_kernel<<<1, 512, 0, s2>>>();
    scan_apply_kernel<<<NB_SCAN, 256, 0, s2>>>();
    fill_kernel<<<nb_edge, TPB, 0, s2>>>(src, dst);
    cudaEventRecord(eJoin, s2);

    // main stream: layer-0 GEMM overlaps the CSR build
    gemm_kernel<<<nb_gemm, TPB>>>(x, W[0], NF);
    cudaStreamWaitEvent(0, eJoin, 0);
    gather_kernel<<<nb_gath, TPB>>>(B[0], nullptr);

    for (int l = 1; l < 4; l++) {
        float* dest = (l == 3) ? out : nullptr;    // nullptr -> g_h
        gemm_kernel<<<nb_gemm, TPB>>>(nullptr, W[l], HD);
        gather_kernel<<<nb_gath, TPB>>>(B[l], dest);
    }

    // cleanup outside capture (destruction deferred until queued work drains)
    if (cap == cudaStreamCaptureStatusNone) {
        cudaEventDestroy(eFork);
        cudaEventDestroy(eJoin);
        cudaStreamDestroy(s2);
    }
}